// round 1
// baseline (speedup 1.0000x reference)
#include <cuda_runtime.h>
#include <math.h>

// Shapes (fixed for this problem)
//  B=8, S=4096, D=1024, H=16, K=256, DH=64

// ---------------- device scratch ----------------
__device__ int   g_len[8];
__device__ float g_inv[8];
__device__ float g_cp[2 * 8 * 256];                       // masked column sums of proj
__device__ float g_hp[(size_t)2 * 8 * 256 * 1024];        // P^T @ hs   [t][b][k][d]
__device__ float g_k [(size_t)8 * 16 * 256 * 64];         // [b][h][k][dh]
__device__ float g_v [(size_t)8 * 16 * 256 * 64];
__device__ float g_q [(size_t)8 * 16 * 4096 * 64];        // [b][h][s][dh]

// ---------------- lengths ----------------
__global__ void len_kernel(const float* __restrict__ mask) {
    int b = blockIdx.x;
    int cnt = 0;
    for (int s = threadIdx.x; s < 4096; s += 256)
        cnt += (mask[b * 4096 + s] > -1.0f) ? 1 : 0;
    #pragma unroll
    for (int o = 16; o; o >>= 1) cnt += __shfl_xor_sync(0xffffffffu, cnt, o);
    __shared__ int wsum[8];
    if ((threadIdx.x & 31) == 0) wsum[threadIdx.x >> 5] = cnt;
    __syncthreads();
    if (threadIdx.x == 0) {
        int tot = 0;
        #pragma unroll
        for (int i = 0; i < 8; i++) tot += wsum[i];
        g_len[b] = tot;
        g_inv[b] = rsqrtf((float)tot);
    }
}

// ---------------- masked column sums of proj: cp[t][b][k] = sum_{s<len} p[s][k] ----
__global__ void cp_kernel(const float* __restrict__ pk, const float* __restrict__ pv) {
    int t = blockIdx.z, b = blockIdx.y, k0 = blockIdx.x * 64;
    const float* p = t ? pv : pk;
    int len = g_len[b];
    int kl = threadIdx.x & 63, sp = threadIdx.x >> 6;
    float sum = 0.f;
    for (int s = sp; s < len; s += 4) sum += p[s * 256 + k0 + kl];
    __shared__ float red[4][64];
    red[sp][kl] = sum;
    __syncthreads();
    if (sp == 0)
        g_cp[(t * 8 + b) * 256 + k0 + kl] =
            red[0][kl] + red[1][kl] + red[2][kl] + red[3][kl];
}

// ---------------- hp[t][b][k][d] = sum_{s<len} p[s][k] * hs[b][s][d] ----------------
__global__ void proj_kernel(const float* __restrict__ hs,
                            const float* __restrict__ pk,
                            const float* __restrict__ pv) {
    int z = blockIdx.z;
    int t = z >> 3, b = z & 7;
    const float* p = t ? pv : pk;
    int k0 = blockIdx.y * 64, d0 = blockIdx.x * 64;
    int len = g_len[b];

    __shared__ __align__(16) float As[32][64];   // p chunk  [s][k]
    __shared__ __align__(16) float Bs[32][64];   // hs chunk [s][d]

    int tx = threadIdx.x & 15, ty = threadIdx.x >> 4;
    int lkk = threadIdx.x & 63, lsb = threadIdx.x >> 6;

    float acc[4][4] = {};
    const float* hsb = hs + (size_t)b * 4096 * 1024;

    for (int s0 = 0; s0 < len; s0 += 32) {
        #pragma unroll
        for (int u = 0; u < 8; u++) {
            int ss = lsb * 8 + u;
            int s  = s0 + ss;
            As[ss][lkk] = (s < len) ? p[s * 256 + k0 + lkk] : 0.f;
            Bs[ss][lkk] = (s < len) ? hsb[(size_t)s * 1024 + d0 + lkk] : 0.f;
        }
        __syncthreads();
        #pragma unroll
        for (int ss = 0; ss < 32; ss++) {
            float4 av = *(const float4*)&As[ss][ty * 4];
            float4 bv = *(const float4*)&Bs[ss][tx * 4];
            float a[4] = {av.x, av.y, av.z, av.w};
            float bb[4] = {bv.x, bv.y, bv.z, bv.w};
            #pragma unroll
            for (int i = 0; i < 4; i++)
                #pragma unroll
                for (int j = 0; j < 4; j++)
                    acc[i][j] += a[i] * bb[j];
        }
        __syncthreads();
    }
    size_t base = ((size_t)(t * 8 + b) * 256 + k0 + ty * 4) * 1024 + d0 + tx * 4;
    #pragma unroll
    for (int i = 0; i < 4; i++) {
        float4 o = {acc[i][0], acc[i][1], acc[i][2], acc[i][3]};
        *(float4*)&g_hp[base + (size_t)i * 1024] = o;
    }
}

// ---------------- common tile: C[r][d] = sum_e A[r][e] * W[d][e] ----------------
__device__ __forceinline__ void gemm_xwT_64x64(const float* __restrict__ A,
                                               const float* __restrict__ W,
                                               int row0, int col0, float acc[4][4]) {
    __shared__ __align__(16) float As[32][68];
    __shared__ __align__(16) float Ws[32][68];
    int tid = threadIdx.x;
    int tx = tid & 15, ty = tid >> 4;
    int ee = tid & 31, r8 = tid >> 5;

    for (int e0 = 0; e0 < 1024; e0 += 32) {
        #pragma unroll
        for (int u = 0; u < 8; u++) {
            int rr = r8 * 8 + u;
            As[ee][rr] = A[(size_t)(row0 + rr) * 1024 + e0 + ee];
            Ws[ee][rr] = W[(size_t)(col0 + rr) * 1024 + e0 + ee];
        }
        __syncthreads();
        #pragma unroll
        for (int e = 0; e < 32; e++) {
            float4 av = *(const float4*)&As[e][ty * 4];
            float4 wv = *(const float4*)&Ws[e][tx * 4];
            float a[4] = {av.x, av.y, av.z, av.w};
            float w[4] = {wv.x, wv.y, wv.z, wv.w};
            #pragma unroll
            for (int i = 0; i < 4; i++)
                #pragma unroll
                for (int j = 0; j < 4; j++)
                    acc[i][j] += a[i] * w[j];
        }
        __syncthreads();
    }
}

// ---------------- Q = hs @ Wq^T + bq  -> g_q[b][h][s][dh] ----------------
__global__ void gemmw_q_kernel(const float* __restrict__ hs,
                               const float* __restrict__ Wq,
                               const float* __restrict__ bq) {
    int col0 = blockIdx.x * 64, row0 = blockIdx.y * 64;
    float acc[4][4] = {};
    gemm_xwT_64x64(hs, Wq, row0, col0, acc);
    int tx = threadIdx.x & 15, ty = threadIdx.x >> 4;
    int r = row0 + ty * 4;
    int b = r >> 12, s = r & 4095;
    int d = col0 + tx * 4;
    int h = d >> 6, dh = d & 63;
    #pragma unroll
    for (int i = 0; i < 4; i++) {
        float4 o = {acc[i][0] + bq[d + 0], acc[i][1] + bq[d + 1],
                    acc[i][2] + bq[d + 2], acc[i][3] + bq[d + 3]};
        *(float4*)&g_q[(((size_t)b * 16 + h) * 4096 + (s + i)) * 64 + dh] = o;
    }
}

// ---------------- K/V = (hp @ W^T + cp⊗bias) * inv  -> g_k/g_v[b][h][k][dh] --------
__global__ void gemmw_kv_kernel(const float* __restrict__ W,
                                const float* __restrict__ bias, int t) {
    int col0 = blockIdx.x * 64, row0 = blockIdx.y * 64;
    const float* A = g_hp + (size_t)t * 2048 * 1024;
    float acc[4][4] = {};
    gemm_xwT_64x64(A, W, row0, col0, acc);
    int tx = threadIdx.x & 15, ty = threadIdx.x >> 4;
    int r = row0 + ty * 4;
    int b = r >> 8;
    int d = col0 + tx * 4;
    int h = d >> 6, dh = d & 63;
    float inv = g_inv[b];
    float* outp = t ? g_v : g_k;
    const float* cpp = g_cp + t * 2048;
    #pragma unroll
    for (int i = 0; i < 4; i++) {
        int kk = (r + i) & 255;
        float c = cpp[b * 256 + kk];
        float4 o = {(acc[i][0] + c * bias[d + 0]) * inv,
                    (acc[i][1] + c * bias[d + 1]) * inv,
                    (acc[i][2] + c * bias[d + 2]) * inv,
                    (acc[i][3] + c * bias[d + 3]) * inv};
        *(float4*)&outp[(((size_t)b * 16 + h) * 256 + kk) * 64 + dh] = o;
    }
}

// ---------------- attention: softmax(q k^T / 8) v ----------------
__global__ void attn_kernel(float* __restrict__ out) {
    int s0 = blockIdx.x * 64, h = blockIdx.y, b = blockIdx.z;
    const float* qp = g_q + (((size_t)b * 16 + h) * 4096 + s0) * 64;
    const float* kp = g_k + ((size_t)b * 16 + h) * 256 * 64;
    const float* vp = g_v + ((size_t)b * 16 + h) * 256 * 64;

    __shared__ float bufA[64 * 65];
    __shared__ float bufB[64 * 65];

    int tid = threadIdx.x, tx = tid & 15, ty = tid >> 4;
    int e = tid & 63, rb = tid >> 6;

    // load q transposed: bufA[e][r]
    #pragma unroll
    for (int u = 0; u < 16; u++) {
        int r = rb * 16 + u;
        bufA[e * 65 + r] = qp[r * 64 + e];
    }

    float acc[4][16];
    #pragma unroll
    for (int i = 0; i < 4; i++)
        #pragma unroll
        for (int jj = 0; jj < 16; jj++) acc[i][jj] = 0.f;

    // scores = q @ k^T, in 4 chunks of 64 columns
    #pragma unroll
    for (int ch = 0; ch < 4; ch++) {
        __syncthreads();
        #pragma unroll
        for (int u = 0; u < 16; u++) {
            int c = rb * 16 + u;
            bufB[e * 65 + c] = kp[(ch * 64 + c) * 64 + e];   // transposed: [e][c]
        }
        __syncthreads();
        #pragma unroll
        for (int ee = 0; ee < 64; ee++) {
            float a[4], bb[4];
            #pragma unroll
            for (int i = 0; i < 4; i++) a[i] = bufA[ee * 65 + ty * 4 + i];
            #pragma unroll
            for (int j = 0; j < 4; j++) bb[j] = bufB[ee * 65 + tx * 4 + j];
            #pragma unroll
            for (int i = 0; i < 4; i++)
                #pragma unroll
                for (int j = 0; j < 4; j++)
                    acc[i][ch * 4 + j] += a[i] * bb[j];
        }
    }

    // softmax over 256 cols; each row split across 16 threads (same ty group)
    const float scale = 0.125f;  // 1/sqrt(64)
    #pragma unroll
    for (int i = 0; i < 4; i++) {
        float m = -1e30f;
        #pragma unroll
        for (int jj = 0; jj < 16; jj++) {
            acc[i][jj] *= scale;
            m = fmaxf(m, acc[i][jj]);
        }
        #pragma unroll
        for (int o = 8; o; o >>= 1) m = fmaxf(m, __shfl_xor_sync(0xffffffffu, m, o));
        float s = 0.f;
        #pragma unroll
        for (int jj = 0; jj < 16; jj++) {
            float p = __expf(acc[i][jj] - m);
            acc[i][jj] = p;
            s += p;
        }
        #pragma unroll
        for (int o = 8; o; o >>= 1) s += __shfl_xor_sync(0xffffffffu, s, o);
        float rinv = 1.0f / s;
        #pragma unroll
        for (int jj = 0; jj < 16; jj++) acc[i][jj] *= rinv;
    }

    // ctx = probs @ v
    float ctx[4][4] = {};
    #pragma unroll
    for (int ch = 0; ch < 4; ch++) {
        __syncthreads();
        // probs transposed into bufA: [c][r]
        #pragma unroll
        for (int j = 0; j < 4; j++)
            #pragma unroll
            for (int i = 0; i < 4; i++)
                bufA[(tx * 4 + j) * 65 + ty * 4 + i] = acc[i][ch * 4 + j];
        // v natural into bufB: [c][d]
        #pragma unroll
        for (int u = 0; u < 16; u++) {
            int c = rb * 16 + u;
            bufB[c * 65 + e] = vp[(ch * 64 + c) * 64 + e];
        }
        __syncthreads();
        #pragma unroll
        for (int c = 0; c < 64; c++) {
            float a[4], bb[4];
            #pragma unroll
            for (int i = 0; i < 4; i++) a[i] = bufA[c * 65 + ty * 4 + i];
            #pragma unroll
            for (int j = 0; j < 4; j++) bb[j] = bufB[c * 65 + tx * 4 + j];
            #pragma unroll
            for (int i = 0; i < 4; i++)
                #pragma unroll
                for (int j = 0; j < 4; j++)
                    ctx[i][j] += a[i] * bb[j];
        }
    }

    #pragma unroll
    for (int i = 0; i < 4; i++) {
        float4 o = {ctx[i][0], ctx[i][1], ctx[i][2], ctx[i][3]};
        *(float4*)&out[((size_t)b * 4096 + s0 + ty * 4 + i) * 1024 + h * 64 + tx * 4] = o;
    }
}

// ---------------- launch ----------------
extern "C" void kernel_launch(void* const* d_in, const int* in_sizes, int n_in,
                              void* d_out, int out_size) {
    const float* hs   = (const float*)d_in[0];
    const float* mask = (const float*)d_in[1];
    const float* Wq   = (const float*)d_in[2];
    const float* bq   = (const float*)d_in[3];
    const float* Wk   = (const float*)d_in[4];
    const float* bk   = (const float*)d_in[5];
    const float* Wv   = (const float*)d_in[6];
    const float* bv   = (const float*)d_in[7];
    const float* pk   = (const float*)d_in[8];
    const float* pv   = (const float*)d_in[9];
    float* out = (float*)d_out;

    len_kernel<<<8, 256>>>(mask);
    cp_kernel<<<dim3(4, 8, 2), 256>>>(pk, pv);
    proj_kernel<<<dim3(16, 4, 16), 256>>>(hs, pk, pv);
    gemmw_kv_kernel<<<dim3(16, 32), 256>>>(Wk, bk, 0);
    gemmw_kv_kernel<<<dim3(16, 32), 256>>>(Wv, bv, 1);
    gemmw_q_kernel<<<dim3(16, 512), 256>>>(hs, Wq, bq);
    attn_kernel<<<dim3(64, 16, 8), 256>>>(out);
}

// round 10
// speedup vs baseline: 1.3749x; 1.3749x over previous
#include <cuda_runtime.h>
#include <cuda_bf16.h>
#include <cstdint>
#include <math.h>

// Shapes: B=8, S=4096, D=1024, H=16, K=256, DH=64
// R10 = R8 resubmitted (R3..R9: infra failures — kernel never executed).

// ---------------- device scratch ----------------
__device__ int   g_len[8];
__device__ float g_inv[8];
__device__ float g_cp[2 * 8 * 256];
__device__ float g_hp[(size_t)2 * 8 * 256 * 1024];        // [t][b][k][d]
__device__ float g_k [(size_t)8 * 16 * 256 * 64];
__device__ float g_v [(size_t)8 * 16 * 256 * 64];
__device__ float g_q [(size_t)8 * 16 * 4096 * 64];

// ---------------- mma helpers ----------------
__device__ __forceinline__ uint32_t smem_u32(const void* p) {
    uint32_t a;
    asm("{ .reg .u64 t; cvta.to.shared.u64 t, %1; cvt.u32.u64 %0, t; }" : "=r"(a) : "l"(p));
    return a;
}
__device__ __forceinline__ void ldsm_x4(uint32_t& r0, uint32_t& r1, uint32_t& r2, uint32_t& r3,
                                        uint32_t addr) {
    asm volatile("ldmatrix.sync.aligned.m8n8.x4.shared.b16 {%0,%1,%2,%3}, [%4];"
                 : "=r"(r0), "=r"(r1), "=r"(r2), "=r"(r3) : "r"(addr));
}
__device__ __forceinline__ void mma_bf16(float* c, const uint32_t* a, uint32_t b0, uint32_t b1) {
    asm volatile(
        "mma.sync.aligned.m16n8k16.row.col.f32.bf16.bf16.f32 "
        "{%0,%1,%2,%3}, {%4,%5,%6,%7}, {%8,%9}, {%0,%1,%2,%3};"
        : "+f"(c[0]), "+f"(c[1]), "+f"(c[2]), "+f"(c[3])
        : "r"(a[0]), "r"(a[1]), "r"(a[2]), "r"(a[3]), "r"(b0), "r"(b1));
}
__device__ __forceinline__ void split_pack(float x, float y, uint32_t& h, uint32_t& l) {
    __nv_bfloat162 hv = __floats2bfloat162_rn(x, y);
    float hx = __bfloat162float(__low2bfloat16(hv));
    float hy = __bfloat162float(__high2bfloat16(hv));
    __nv_bfloat162 lv = __floats2bfloat162_rn(x - hx, y - hy);
    h = *reinterpret_cast<uint32_t*>(&hv);
    l = *reinterpret_cast<uint32_t*>(&lv);
}

static constexpr int LDT = 40;   // GEMM smem row stride (bf16 units)

// one k32 chunk of the 3-product split mma, warp tile 64x32
__device__ __forceinline__ void compute_chunk(uint32_t AhU, uint32_t AlU,
                                              uint32_t BhU, uint32_t BlU,
                                              int wrow, int wcol, uint32_t laneOff,
                                              float acc[4][4][4]) {
    #pragma unroll
    for (int ks = 0; ks < 32; ks += 16) {
        uint32_t aH[4][4], aL[4][4], bH[4][2], bL[4][2];
        #pragma unroll
        for (int rt = 0; rt < 4; rt++) {
            uint32_t off = (uint32_t)(((wrow + rt * 16) * LDT + ks) * 2) + laneOff;
            ldsm_x4(aH[rt][0], aH[rt][1], aH[rt][2], aH[rt][3], AhU + off);
            ldsm_x4(aL[rt][0], aL[rt][1], aL[rt][2], aL[rt][3], AlU + off);
        }
        #pragma unroll
        for (int bt = 0; bt < 2; bt++) {
            uint32_t off = (uint32_t)(((wcol + bt * 16) * LDT + ks) * 2) + laneOff;
            uint32_t r0, r1, r2, r3;
            ldsm_x4(r0, r1, r2, r3, BhU + off);
            bH[bt * 2][0] = r0; bH[bt * 2][1] = r2;
            bH[bt * 2 + 1][0] = r1; bH[bt * 2 + 1][1] = r3;
            ldsm_x4(r0, r1, r2, r3, BlU + off);
            bL[bt * 2][0] = r0; bL[bt * 2][1] = r2;
            bL[bt * 2 + 1][0] = r1; bL[bt * 2 + 1][1] = r3;
        }
        #pragma unroll
        for (int rt = 0; rt < 4; rt++)
            #pragma unroll
            for (int ct = 0; ct < 4; ct++) {
                mma_bf16(acc[rt][ct], aH[rt], bH[ct][0], bH[ct][1]);
                mma_bf16(acc[rt][ct], aH[rt], bL[ct][0], bL[ct][1]);
                mma_bf16(acc[rt][ct], aL[rt], bH[ct][0], bH[ct][1]);
            }
    }
}

// ---------------- X @ W^T mainloop ----------------
__device__ __forceinline__ void gemm_xwT_mma(const float* __restrict__ A,
                                             const float* __restrict__ W,
                                             int row0, int col0,
                                             uint16_t* sAh, uint16_t* sAl,
                                             uint16_t* sBh, uint16_t* sBl,
                                             float acc[4][4][4]) {
    int tid = threadIdx.x, wid = tid >> 5, lid = tid & 31;
    int wrow = (wid >> 2) * 64, wcol = (wid & 3) * 32;
    int qr = lid & 15;
    int qc = (lid & 16) ? 8 : 0;
    uint32_t laneOff = (uint32_t)((qr * LDT + qc) * 2);
    uint32_t AhU = smem_u32(sAh), AlU = smem_u32(sAl);
    uint32_t BhU = smem_u32(sBh), BlU = smem_u32(sBl);

    for (int ci = 0; ci < 32; ci++) {
        int e0 = ci * 32;
        #pragma unroll
        for (int it = 0; it < 4; it++) {
            int lin = it * 256 + tid;
            int r = lin >> 3;
            int c = (lin & 7) * 4;
            float4 a = *(const float4*)(A + (size_t)(row0 + r) * 1024 + e0 + c);
            uint32_t h0, l0, h1, l1;
            split_pack(a.x, a.y, h0, l0);
            split_pack(a.z, a.w, h1, l1);
            *(uint32_t*)&sAh[r * LDT + c] = h0;  *(uint32_t*)&sAh[r * LDT + c + 2] = h1;
            *(uint32_t*)&sAl[r * LDT + c] = l0;  *(uint32_t*)&sAl[r * LDT + c + 2] = l1;
            float4 b = *(const float4*)(W + (size_t)(col0 + r) * 1024 + e0 + c);
            split_pack(b.x, b.y, h0, l0);
            split_pack(b.z, b.w, h1, l1);
            *(uint32_t*)&sBh[r * LDT + c] = h0;  *(uint32_t*)&sBh[r * LDT + c + 2] = h1;
            *(uint32_t*)&sBl[r * LDT + c] = l0;  *(uint32_t*)&sBl[r * LDT + c + 2] = l1;
        }
        __syncthreads();
        compute_chunk(AhU, AlU, BhU, BlU, wrow, wcol, laneOff, acc);
        __syncthreads();
    }
}

// ---------------- Q = hs @ Wq^T + bq ----------------
__global__ void __launch_bounds__(256) q_mma(const float* __restrict__ hs,
                                             const float* __restrict__ Wq,
                                             const float* __restrict__ bq) {
    __shared__ uint16_t sAh[128 * LDT], sAl[128 * LDT], sBh[128 * LDT], sBl[128 * LDT];
    int row0 = blockIdx.y * 128, col0 = blockIdx.x * 128;
    float acc[4][4][4] = {};
    gemm_xwT_mma(hs, Wq, row0, col0, sAh, sAl, sBh, sBl, acc);

    int tid = threadIdx.x, wid = tid >> 5, lid = tid & 31;
    int gid = lid >> 2, tig = lid & 3;
    int wrow = (wid >> 2) * 64, wcol = (wid & 3) * 32;
    #pragma unroll
    for (int rt = 0; rt < 4; rt++)
        #pragma unroll
        for (int ct = 0; ct < 4; ct++) {
            int d = col0 + wcol + ct * 8 + tig * 2;
            int h = d >> 6, dh = d & 63;
            float b0 = bq[d], b1 = bq[d + 1];
            #pragma unroll
            for (int hf = 0; hf < 2; hf++) {
                int rg = row0 + wrow + rt * 16 + gid + hf * 8;
                int b = rg >> 12, s = rg & 4095;
                float2 o = {acc[rt][ct][hf * 2 + 0] + b0, acc[rt][ct][hf * 2 + 1] + b1};
                *(float2*)&g_q[(((size_t)b * 16 + h) * 4096 + s) * 64 + dh] = o;
            }
        }
}

// ---------------- K/V = (hp @ W^T + cp*bias) * inv ----------------
__global__ void __launch_bounds__(256) kv_mma(const float* __restrict__ Wk,
                                              const float* __restrict__ bk,
                                              const float* __restrict__ Wv,
                                              const float* __restrict__ bv) {
    __shared__ uint16_t sAh[128 * LDT], sAl[128 * LDT], sBh[128 * LDT], sBl[128 * LDT];
    int t = blockIdx.z;
    int row0 = blockIdx.y * 128, col0 = blockIdx.x * 128;
    const float* W = t ? Wv : Wk;
    const float* bias = t ? bv : bk;
    const float* A = g_hp + (size_t)t * 2048 * 1024;
    float* outp = t ? g_v : g_k;

    float acc[4][4][4] = {};
    gemm_xwT_mma(A, W, row0, col0, sAh, sAl, sBh, sBl, acc);

    int tid = threadIdx.x, wid = tid >> 5, lid = tid & 31;
    int gid = lid >> 2, tig = lid & 3;
    int wrow = (wid >> 2) * 64, wcol = (wid & 3) * 32;
    #pragma unroll
    for (int rt = 0; rt < 4; rt++)
        #pragma unroll
        for (int ct = 0; ct < 4; ct++) {
            int d = col0 + wcol + ct * 8 + tig * 2;
            int h = d >> 6, dh = d & 63;
            float b0 = bias[d], b1 = bias[d + 1];
            #pragma unroll
            for (int hf = 0; hf < 2; hf++) {
                int rg = row0 + wrow + rt * 16 + gid + hf * 8;
                int b = rg >> 8, kk = rg & 255;
                float inv = g_inv[b];
                float cv = g_cp[t * 2048 + b * 256 + kk];
                float2 o = {(acc[rt][ct][hf * 2 + 0] + cv * b0) * inv,
                            (acc[rt][ct][hf * 2 + 1] + cv * b1) * inv};
                *(float2*)&outp[(((size_t)b * 16 + h) * 256 + kk) * 64 + dh] = o;
            }
        }
}

// ---------------- hp = P^T @ hs (mma, masked) ----------------
__global__ void __launch_bounds__(256) proj_mma(const float* __restrict__ hs,
                                                const float* __restrict__ pk,
                                                const float* __restrict__ pv) {
    __shared__ uint16_t sAh[128 * LDT], sAl[128 * LDT], sBh[128 * LDT], sBl[128 * LDT];
    int z = blockIdx.z;
    int t = z >> 3, b = z & 7;
    const float* p = t ? pv : pk;
    const float* hsb = hs + (size_t)b * 4096 * 1024;
    int k0 = blockIdx.y * 128, d0 = blockIdx.x * 128;
    int len = g_len[b];

    int tid = threadIdx.x, wid = tid >> 5, lid = tid & 31;
    int wrow = (wid >> 2) * 64, wcol = (wid & 3) * 32;
    int qr = lid & 15;
    int qc = (lid & 16) ? 8 : 0;
    uint32_t laneOff = (uint32_t)((qr * LDT + qc) * 2);
    uint32_t AhU = smem_u32(sAh), AlU = smem_u32(sAl);
    uint32_t BhU = smem_u32(sBh), BlU = smem_u32(sBl);

    float acc[4][4][4] = {};

    for (int s0 = 0; s0 < len; s0 += 32) {
        #pragma unroll
        for (int it = 0; it < 4; it++) {
            int lin = it * 256 + tid;
            int s = lin >> 5;
            int c = (lin & 31) * 4;
            bool ok = (s0 + s) < len;
            float4 a = ok ? *(const float4*)(p + (size_t)(s0 + s) * 256 + k0 + c)
                          : make_float4(0.f, 0.f, 0.f, 0.f);
            float4 bvv = ok ? *(const float4*)(hsb + (size_t)(s0 + s) * 1024 + d0 + c)
                            : make_float4(0.f, 0.f, 0.f, 0.f);
            float av[4] = {a.x, a.y, a.z, a.w};
            float bw[4] = {bvv.x, bvv.y, bvv.z, bvv.w};
            #pragma unroll
            for (int i = 0; i < 4; i++) {
                __nv_bfloat16 hb = __float2bfloat16(av[i]);
                __nv_bfloat16 lb = __float2bfloat16(av[i] - __bfloat162float(hb));
                sAh[(c + i) * LDT + s] = __bfloat16_as_ushort(hb);
                sAl[(c + i) * LDT + s] = __bfloat16_as_ushort(lb);
                hb = __float2bfloat16(bw[i]);
                lb = __float2bfloat16(bw[i] - __bfloat162float(hb));
                sBh[(c + i) * LDT + s] = __bfloat16_as_ushort(hb);
                sBl[(c + i) * LDT + s] = __bfloat16_as_ushort(lb);
            }
        }
        __syncthreads();
        compute_chunk(AhU, AlU, BhU, BlU, wrow, wcol, laneOff, acc);
        __syncthreads();
    }

    int gid = lid >> 2, tig = lid & 3;
    #pragma unroll
    for (int rt = 0; rt < 4; rt++)
        #pragma unroll
        for (int ct = 0; ct < 4; ct++) {
            int dd = d0 + wcol + ct * 8 + tig * 2;
            #pragma unroll
            for (int hf = 0; hf < 2; hf++) {
                int rk = k0 + wrow + rt * 16 + gid + hf * 8;
                float2 o = {acc[rt][ct][hf * 2 + 0], acc[rt][ct][hf * 2 + 1]};
                *(float2*)&g_hp[((size_t)z * 256 + rk) * 1024 + dd] = o;
            }
        }
}

// ---------------- lengths ----------------
__global__ void len_kernel(const float* __restrict__ mask) {
    int b = blockIdx.x;
    int cnt = 0;
    for (int s = threadIdx.x; s < 4096; s += 256)
        cnt += (mask[b * 4096 + s] > -1.0f) ? 1 : 0;
    #pragma unroll
    for (int o = 16; o; o >>= 1) cnt += __shfl_xor_sync(0xffffffffu, cnt, o);
    __shared__ int wsum[8];
    if ((threadIdx.x & 31) == 0) wsum[threadIdx.x >> 5] = cnt;
    __syncthreads();
    if (threadIdx.x == 0) {
        int tot = 0;
        #pragma unroll
        for (int i = 0; i < 8; i++) tot += wsum[i];
        g_len[b] = tot;
        g_inv[b] = rsqrtf((float)tot);
    }
}

// ---------------- masked column sums of proj ----------------
__global__ void cp_kernel(const float* __restrict__ pk, const float* __restrict__ pv) {
    int t = blockIdx.z, b = blockIdx.y, k0 = blockIdx.x * 64;
    const float* p = t ? pv : pk;
    int len = g_len[b];
    int kl = threadIdx.x & 63, sp = threadIdx.x >> 6;
    float sum = 0.f;
    for (int s = sp; s < len; s += 4) sum += p[s * 256 + k0 + kl];
    __shared__ float red[4][64];
    red[sp][kl] = sum;
    __syncthreads();
    if (sp == 0)
        g_cp[(t * 8 + b) * 256 + k0 + kl] =
            red[0][kl] + red[1][kl] + red[2][kl] + red[3][kl];
}

// ---------------- attention via mma: 64 q-rows per block, full K=256 ----------------
static constexpr int LQ = 72;    // Q/K smem stride (bf16)
static constexpr int LP = 264;   // P/VT smem stride (bf16)
static constexpr int OFF_QH = 0;
static constexpr int OFF_QL = 9216;
static constexpr int OFF_KH = 18432;
static constexpr int OFF_KL = 55296;      // K region ends 92160
static constexpr int OFF_PH = 0;          // reuses Q region (dead)
static constexpr int OFF_PL = 33792;
static constexpr int OFF_VH = 67584;      // reuses K region (dead)
static constexpr int OFF_VL = 101376;     // ends 135168
static constexpr int OFF_RMAX = 135168;
static constexpr int OFF_RSUM = 137216;
static constexpr int SMEM_ATTN = 139264;

__global__ void __launch_bounds__(256) attn_mma(float* __restrict__ out) {
    extern __shared__ char smem[];
    int s0 = blockIdx.x * 64, h = blockIdx.y, b = blockIdx.z;
    const float* qp = g_q + (((size_t)b * 16 + h) * 4096 + s0) * 64;
    const float* kp = g_k + ((size_t)b * 16 + h) * 256 * 64;
    const float* vp = g_v + ((size_t)b * 16 + h) * 256 * 64;

    int tid = threadIdx.x, wid = tid >> 5, lid = tid & 31;
    int gid = lid >> 2, tig = lid & 3;
    int qr = lid & 15;
    int qc = (lid & 16) ? 8 : 0;
    uint32_t S = smem_u32(smem);
    float* rmax = (float*)(smem + OFF_RMAX);
    float* rsum = (float*)(smem + OFF_RSUM);

    // ---- phase 1 loads: Q [64][64], K [256][64], split hi/lo ----
    #pragma unroll
    for (int it = 0; it < 4; it++) {
        int lin = it * 256 + tid;
        int r = lin >> 4, c = (lin & 15) * 4;
        float4 a = *(const float4*)(qp + r * 64 + c);
        uint32_t h0, l0, h1, l1;
        split_pack(a.x, a.y, h0, l0);
        split_pack(a.z, a.w, h1, l1);
        *(uint32_t*)(smem + OFF_QH + (r * LQ + c) * 2) = h0;
        *(uint32_t*)(smem + OFF_QH + (r * LQ + c + 2) * 2) = h1;
        *(uint32_t*)(smem + OFF_QL + (r * LQ + c) * 2) = l0;
        *(uint32_t*)(smem + OFF_QL + (r * LQ + c + 2) * 2) = l1;
    }
    #pragma unroll
    for (int it = 0; it < 16; it++) {
        int lin = it * 256 + tid;
        int r = lin >> 4, c = (lin & 15) * 4;
        float4 a = *(const float4*)(kp + r * 64 + c);
        uint32_t h0, l0, h1, l1;
        split_pack(a.x, a.y, h0, l0);
        split_pack(a.z, a.w, h1, l1);
        *(uint32_t*)(smem + OFF_KH + (r * LQ + c) * 2) = h0;
        *(uint32_t*)(smem + OFF_KH + (r * LQ + c + 2) * 2) = h1;
        *(uint32_t*)(smem + OFF_KL + (r * LQ + c) * 2) = l0;
        *(uint32_t*)(smem + OFF_KL + (r * LQ + c + 2) * 2) = l1;
    }
    __syncthreads();

    // ---- scores: S[64][256], warp wid covers cols wid*32..+32 ----
    float acc[4][4][4] = {};
    #pragma unroll
    for (int ks = 0; ks < 64; ks += 16) {
        uint32_t aH[4][4], aL[4][4], bH[4][2], bL[4][2];
        #pragma unroll
        for (int rt = 0; rt < 4; rt++) {
            uint32_t off = (uint32_t)(((rt * 16 + qr) * LQ + ks + qc) * 2);
            ldsm_x4(aH[rt][0], aH[rt][1], aH[rt][2], aH[rt][3], S + OFF_QH + off);
            ldsm_x4(aL[rt][0], aL[rt][1], aL[rt][2], aL[rt][3], S + OFF_QL + off);
        }
        #pragma unroll
        for (int bt = 0; bt < 2; bt++) {
            uint32_t off = (uint32_t)(((wid * 32 + bt * 16 + qr) * LQ + ks + qc) * 2);
            uint32_t r0, r1, r2, r3;
            ldsm_x4(r0, r1, r2, r3, S + OFF_KH + off);
            bH[bt * 2][0] = r0; bH[bt * 2][1] = r2;
            bH[bt * 2 + 1][0] = r1; bH[bt * 2 + 1][1] = r3;
            ldsm_x4(r0, r1, r2, r3, S + OFF_KL + off);
            bL[bt * 2][0] = r0; bL[bt * 2][1] = r2;
            bL[bt * 2 + 1][0] = r1; bL[bt * 2 + 1][1] = r3;
        }
        #pragma unroll
        for (int rt = 0; rt < 4; rt++)
            #pragma unroll
            for (int ct = 0; ct < 4; ct++) {
                mma_bf16(acc[rt][ct], aH[rt], bH[ct][0], bH[ct][1]);
                mma_bf16(acc[rt][ct], aH[rt], bL[ct][0], bL[ct][1]);
                mma_bf16(acc[rt][ct], aL[rt], bH[ct][0], bH[ct][1]);
            }
    }
    __syncthreads();   // Q/K smem dead from here

    // ---- load V transposed+split into VT region (overlaps dead K) ----
    #pragma unroll
    for (int it = 0; it < 16; it++) {
        int lin = it * 256 + tid;
        int k = lin >> 4, d = (lin & 15) * 4;
        float4 v = *(const float4*)(vp + k * 64 + d);
        float vv[4] = {v.x, v.y, v.z, v.w};
        #pragma unroll
        for (int i = 0; i < 4; i++) {
            __nv_bfloat16 hb = __float2bfloat16(vv[i]);
            __nv_bfloat16 lb = __float2bfloat16(vv[i] - __bfloat162float(hb));
            *(uint16_t*)(smem + OFF_VH + ((d + i) * LP + k) * 2) = __bfloat16_as_ushort(hb);
            *(uint16_t*)(smem + OFF_VL + ((d + i) * LP + k) * 2) = __bfloat16_as_ushort(lb);
        }
    }

    // ---- softmax over 256 cols (rows: rt*16+gid+hf*8; thread holds 8 cols/row) ----
    const float scale = 0.125f;
    float gm[8], gs[8];
    #pragma unroll
    for (int rt = 0; rt < 4; rt++)
        #pragma unroll
        for (int hf = 0; hf < 2; hf++) {
            float m = -1e30f;
            #pragma unroll
            for (int ct = 0; ct < 4; ct++)
                #pragma unroll
                for (int e = 0; e < 2; e++) {
                    acc[rt][ct][hf * 2 + e] *= scale;
                    m = fmaxf(m, acc[rt][ct][hf * 2 + e]);
                }
            m = fmaxf(m, __shfl_xor_sync(0xffffffffu, m, 1));
            m = fmaxf(m, __shfl_xor_sync(0xffffffffu, m, 2));
            if (tig == 0) rmax[(rt * 16 + gid + hf * 8) * 8 + wid] = m;
        }
    __syncthreads();
    #pragma unroll
    for (int rt = 0; rt < 4; rt++)
        #pragma unroll
        for (int hf = 0; hf < 2; hf++) {
            int row = rt * 16 + gid + hf * 8;
            float m = rmax[row * 8 + 0];
            #pragma unroll
            for (int w = 1; w < 8; w++) m = fmaxf(m, rmax[row * 8 + w]);
            gm[rt * 2 + hf] = m;
            float s = 0.f;
            #pragma unroll
            for (int ct = 0; ct < 4; ct++)
                #pragma unroll
                for (int e = 0; e < 2; e++) {
                    float pv2 = __expf(acc[rt][ct][hf * 2 + e] - m);
                    acc[rt][ct][hf * 2 + e] = pv2;
                    s += pv2;
                }
            s += __shfl_xor_sync(0xffffffffu, s, 1);
            s += __shfl_xor_sync(0xffffffffu, s, 2);
            if (tig == 0) rsum[row * 8 + wid] = s;
        }
    __syncthreads();
    #pragma unroll
    for (int rt = 0; rt < 4; rt++)
        #pragma unroll
        for (int hf = 0; hf < 2; hf++) {
            int row = rt * 16 + gid + hf * 8;
            float s = 0.f;
            #pragma unroll
            for (int w = 0; w < 8; w++) s += rsum[row * 8 + w];
            gs[rt * 2 + hf] = 1.0f / s;
        }

    // ---- write probs split into P region (overlaps dead Q) ----
    #pragma unroll
    for (int rt = 0; rt < 4; rt++)
        #pragma unroll
        for (int hf = 0; hf < 2; hf++) {
            int row = rt * 16 + gid + hf * 8;
            float rinv = gs[rt * 2 + hf];
            #pragma unroll
            for (int ct = 0; ct < 4; ct++) {
                int col = wid * 32 + ct * 8 + tig * 2;
                float p0 = acc[rt][ct][hf * 2 + 0] * rinv;
                float p1 = acc[rt][ct][hf * 2 + 1] * rinv;
                uint32_t hh, ll;
                split_pack(p0, p1, hh, ll);
                *(uint32_t*)(smem + OFF_PH + (row * LP + col) * 2) = hh;
                *(uint32_t*)(smem + OFF_PL + (row * LP + col) * 2) = ll;
            }
        }
    __syncthreads();

    // ---- ctx = P[64][256] @ VT[64][256]^T; warp tile 32x16 ----
    float acc2[2][2][4] = {};
    int arow = (wid >> 2) * 32;
    int bcol = (wid & 3) * 16;
    #pragma unroll
    for (int ks = 0; ks < 256; ks += 16) {
        uint32_t aH[2][4], aL[2][4], bH[2][2], bL[2][2];
        #pragma unroll
        for (int rt = 0; rt < 2; rt++) {
            uint32_t off = (uint32_t)(((arow + rt * 16 + qr) * LP + ks + qc) * 2);
            ldsm_x4(aH[rt][0], aH[rt][1], aH[rt][2], aH[rt][3], S + OFF_PH + off);
            ldsm_x4(aL[rt][0], aL[rt][1], aL[rt][2], aL[rt][3], S + OFF_PL + off);
        }
        {
            uint32_t off = (uint32_t)(((bcol + qr) * LP + ks + qc) * 2);
            uint32_t r0, r1, r2, r3;
            ldsm_x4(r0, r1, r2, r3, S + OFF_VH + off);
            bH[0][0] = r0; bH[0][1] = r2;
            bH[1][0] = r1; bH[1][1] = r3;
            ldsm_x4(r0, r1, r2, r3, S + OFF_VL + off);
            bL[0][0] = r0; bL[0][1] = r2;
            bL[1][0] = r1; bL[1][1] = r3;
        }
        #pragma unroll
        for (int rt = 0; rt < 2; rt++)
            #pragma unroll
            for (int cg = 0; cg < 2; cg++) {
                mma_bf16(acc2[rt][cg], aH[rt], bH[cg][0], bH[cg][1]);
                mma_bf16(acc2[rt][cg], aH[rt], bL[cg][0], bL[cg][1]);
                mma_bf16(acc2[rt][cg], aL[rt], bH[cg][0], bH[cg][1]);
            }
    }

    // ---- epilogue: out[b][s0+row][h*64 + col] ----
    #pragma unroll
    for (int rt = 0; rt < 2; rt++)
        #pragma unroll
        for (int cg = 0; cg < 2; cg++) {
            int col = bcol + cg * 8 + tig * 2;
            #pragma unroll
            for (int hf = 0; hf < 2; hf++) {
                int row = arow + rt * 16 + gid + hf * 8;
                float2 o = {acc2[rt][cg][hf * 2 + 0], acc2[rt][cg][hf * 2 + 1]};
                *(float2*)&out[((size_t)b * 4096 + s0 + row) * 1024 + h * 64 + col] = o;
            }
        }
}

// ---------------- launch ----------------
extern "C" void kernel_launch(void* const* d_in, const int* in_sizes, int n_in,
                              void* d_out, int out_size) {
    const float* hs   = (const float*)d_in[0];
    const float* mask = (const float*)d_in[1];
    const float* Wq   = (const float*)d_in[2];
    const float* bq   = (const float*)d_in[3];
    const float* Wk   = (const float*)d_in[4];
    const float* bk   = (const float*)d_in[5];
    const float* Wv   = (const float*)d_in[6];
    const float* bv   = (const float*)d_in[7];
    const float* pk   = (const float*)d_in[8];
    const float* pv   = (const float*)d_in[9];
    float* out = (float*)d_out;

    cudaFuncSetAttribute(attn_mma, cudaFuncAttributeMaxDynamicSharedMemorySize, SMEM_ATTN);

    len_kernel<<<8, 256>>>(mask);
    cp_kernel<<<dim3(4, 8, 2), 256>>>(pk, pv);
    proj_mma<<<dim3(8, 2, 16), 256>>>(hs, pk, pv);
    kv_mma<<<dim3(8, 16, 2), 256>>>(Wk, bk, Wv, bv);
    q_mma<<<dim3(8, 256), 256>>>(hs, Wq, bq);
    attn_mma<<<dim3(64, 16, 8), 256, SMEM_ATTN>>>(out);
}